// round 3
// baseline (speedup 1.0000x reference)
#include <cuda_runtime.h>
#include <cuda_bf16.h>
#include <cstdint>

#define DIM 1024
#define KV_DIM 768
#define NUM_HEADS 16
#define HEAD_DIM 64
#define BATCH 2
#define LQ 4096
#define LKV 1024

// ---------------------------------------------------------------------------
// Scratch (no allocation allowed)
// ---------------------------------------------------------------------------
__device__ float g_q[BATCH * LQ * DIM];
__device__ float g_k[BATCH * LKV * DIM];
__device__ float g_v[BATCH * LKV * DIM];
__device__ float g_attn[BATCH * LQ * DIM];

__device__ __nv_bfloat16 g_xh[BATCH * LQ * DIM];
__device__ __nv_bfloat16 g_xl[BATCH * LQ * DIM];
__device__ __nv_bfloat16 g_yh[BATCH * LKV * KV_DIM];
__device__ __nv_bfloat16 g_yl[BATCH * LKV * KV_DIM];
__device__ __nv_bfloat16 g_ah[BATCH * LQ * DIM];
__device__ __nv_bfloat16 g_al[BATCH * LQ * DIM];
__device__ __nv_bfloat16 g_WqTh[DIM * DIM];
__device__ __nv_bfloat16 g_WqTl[DIM * DIM];
__device__ __nv_bfloat16 g_WkTh[DIM * KV_DIM];
__device__ __nv_bfloat16 g_WkTl[DIM * KV_DIM];
__device__ __nv_bfloat16 g_WvTh[DIM * KV_DIM];
__device__ __nv_bfloat16 g_WvTl[DIM * KV_DIM];
__device__ __nv_bfloat16 g_WoTh[DIM * DIM];
__device__ __nv_bfloat16 g_WoTl[DIM * DIM];

// ---------------------------------------------------------------------------
// mma.sync / ldmatrix / cp.async helpers (all base-target sm_80+ features)
// ---------------------------------------------------------------------------
__device__ __forceinline__ uint32_t smem_u32(const void* p) {
    uint32_t a;
    asm("{ .reg .u64 t; cvta.to.shared.u64 t, %1; cvt.u32.u64 %0, t; }"
        : "=r"(a) : "l"(p));
    return a;
}

#define LDSM4(r, addr) \
    asm volatile("ldmatrix.sync.aligned.m8n8.x4.shared.b16 {%0,%1,%2,%3}, [%4];" \
        : "=r"((r)[0]), "=r"((r)[1]), "=r"((r)[2]), "=r"((r)[3]) : "r"(addr))

#define MMA_BF16(d, a, b0, b1) \
    asm volatile("mma.sync.aligned.m16n8k16.row.col.f32.bf16.bf16.f32 " \
        "{%0,%1,%2,%3}, {%4,%5,%6,%7}, {%8,%9}, {%0,%1,%2,%3};" \
        : "+f"((d)[0]), "+f"((d)[1]), "+f"((d)[2]), "+f"((d)[3]) \
        : "r"((a)[0]), "r"((a)[1]), "r"((a)[2]), "r"((a)[3]), "r"(b0), "r"(b1))

__device__ __forceinline__ void cp16(uint32_t dst, const void* src) {
    asm volatile("cp.async.cg.shared.global [%0], [%1], 16;"
                 :: "r"(dst), "l"(src) : "memory");
}

// ---------------------------------------------------------------------------
// Split fp32 -> bf16 hi + bf16 lo residual. n multiple of 1024.
// ---------------------------------------------------------------------------
__global__ __launch_bounds__(256) void split_kernel(
    const float* __restrict__ x, __nv_bfloat16* __restrict__ h,
    __nv_bfloat16* __restrict__ l)
{
    size_t i = ((size_t)blockIdx.x * 256 + threadIdx.x) * 4;
    float4 v = *reinterpret_cast<const float4*>(x + i);
    __nv_bfloat16 h0 = __float2bfloat16(v.x);
    __nv_bfloat16 h1 = __float2bfloat16(v.y);
    __nv_bfloat16 h2 = __float2bfloat16(v.z);
    __nv_bfloat16 h3 = __float2bfloat16(v.w);
    __nv_bfloat16 l0 = __float2bfloat16(v.x - __bfloat162float(h0));
    __nv_bfloat16 l1 = __float2bfloat16(v.y - __bfloat162float(h1));
    __nv_bfloat16 l2 = __float2bfloat16(v.z - __bfloat162float(h2));
    __nv_bfloat16 l3 = __float2bfloat16(v.w - __bfloat162float(h3));
    reinterpret_cast<__nv_bfloat162*>(h + i)[0] = __nv_bfloat162(h0, h1);
    reinterpret_cast<__nv_bfloat162*>(h + i)[1] = __nv_bfloat162(h2, h3);
    reinterpret_cast<__nv_bfloat162*>(l + i)[0] = __nv_bfloat162(l0, l1);
    reinterpret_cast<__nv_bfloat162*>(l + i)[1] = __nv_bfloat162(l2, l3);
}

// ---------------------------------------------------------------------------
// W [K,N] fp32 -> WT [N,K] bf16 hi/lo (transpose + split)
// ---------------------------------------------------------------------------
__global__ __launch_bounds__(256) void transpose_split_kernel(
    const float* __restrict__ W, __nv_bfloat16* __restrict__ Th,
    __nv_bfloat16* __restrict__ Tl, int K, int N)
{
    __shared__ float t[32][33];
    int n0 = blockIdx.x * 32, k0 = blockIdx.y * 32;
    int tx = threadIdx.x, ty = threadIdx.y;
    #pragma unroll
    for (int r = 0; r < 32; r += 8)
        t[ty + r][tx] = W[(size_t)(k0 + ty + r) * N + n0 + tx];
    __syncthreads();
    #pragma unroll
    for (int r = 0; r < 32; r += 8) {
        float v = t[tx][ty + r];
        __nv_bfloat16 hh = __float2bfloat16(v);
        __nv_bfloat16 ll = __float2bfloat16(v - __bfloat162float(hh));
        size_t o = (size_t)(n0 + ty + r) * K + k0 + tx;
        Th[o] = hh;
        Tl[o] = ll;
    }
}

// ---------------------------------------------------------------------------
// bf16 mma.sync GEMM with 3-term split:
//   C[M,1024] = Ah@Bh^T + Ah@Bl^T + Al@Bh^T + bias
// A: [M,K] bf16 row-major.  B: [1024,K] bf16 row-major (pre-transposed W).
// CTA tile 128x128, K-chunk 64, 8 warps (4m x 2n), warp tile 32x64.
// Smem tile: 128 rows x 128B, chunk-xor swizzle for conflict-free ldmatrix.
// ---------------------------------------------------------------------------
#define TILE_B   16384          // one 128x64 bf16 tile
#define CHUNK_B  (4 * TILE_B)   // Ah, Al, Bh, Bl
#define GEMM_SMEM (2 * CHUNK_B) // double buffer = 128KB

__device__ __forceinline__ void load_chunk(
    uint32_t sbase,
    const __nv_bfloat16* __restrict__ Ah, const __nv_bfloat16* __restrict__ Al,
    const __nv_bfloat16* __restrict__ Bh, const __nv_bfloat16* __restrict__ Bl,
    int m0, int n0, int k0, int K, int tid)
{
    #pragma unroll
    for (int i = 0; i < 4; i++) {
        int idx = i * 256 + tid;      // 0..1023
        int r = idx >> 3;             // row 0..127
        int c = idx & 7;              // 16B chunk 0..7
        uint32_t off = (uint32_t)(r * 128 + ((c ^ (r & 7)) * 16));
        size_t ga = (size_t)(m0 + r) * K + k0 + c * 8;
        size_t gb = (size_t)(n0 + r) * K + k0 + c * 8;
        cp16(sbase + off,              Ah + ga);
        cp16(sbase + TILE_B + off,     Al + ga);
        cp16(sbase + 2 * TILE_B + off, Bh + gb);
        cp16(sbase + 3 * TILE_B + off, Bl + gb);
    }
}

__global__ __launch_bounds__(256) void gemm_tc_kernel(
    const __nv_bfloat16* __restrict__ Ah, const __nv_bfloat16* __restrict__ Al,
    const __nv_bfloat16* __restrict__ Bh, const __nv_bfloat16* __restrict__ Bl,
    const float* __restrict__ bias, float* __restrict__ C,
    int M, int K)
{
    extern __shared__ __align__(1024) char dsm[];
    const int N = 1024;
    int tid = threadIdx.x;
    int lane = tid & 31;
    int wid = tid >> 5;
    int wm = wid & 3;       // m-warp: 32 rows each
    int wn = wid >> 2;      // n-warp: 64 cols each
    int n0 = blockIdx.x * 128, m0 = blockIdx.y * 128;

    uint32_t sb = smem_u32(dsm);
    int nk = K >> 6;

    float acc[2][8][4];
    #pragma unroll
    for (int mt = 0; mt < 2; mt++)
        #pragma unroll
        for (int nt = 0; nt < 8; nt++)
            #pragma unroll
            for (int e = 0; e < 4; e++) acc[mt][nt][e] = 0.f;

    int mi = lane >> 3;     // ldmatrix sub-matrix index 0..3
    int lr = lane & 7;

    load_chunk(sb, Ah, Al, Bh, Bl, m0, n0, 0, K, tid);
    asm volatile("cp.async.commit_group;" ::: "memory");

    for (int i = 0; i < nk; i++) {
        if (i + 1 < nk) {
            load_chunk(sb + ((i + 1) & 1) * CHUNK_B, Ah, Al, Bh, Bl,
                       m0, n0, (i + 1) << 6, K, tid);
            asm volatile("cp.async.commit_group;" ::: "memory");
            asm volatile("cp.async.wait_group 1;" ::: "memory");
        } else {
            asm volatile("cp.async.wait_group 0;" ::: "memory");
        }
        __syncthreads();

        uint32_t base = sb + (i & 1) * CHUNK_B;
        uint32_t sAh = base, sAl = base + TILE_B;
        uint32_t sBh = base + 2 * TILE_B, sBl = base + 3 * TILE_B;

        #pragma unroll
        for (int ks = 0; ks < 4; ks++) {
            uint32_t afh[2][4], afl[2][4];
            #pragma unroll
            for (int mt = 0; mt < 2; mt++) {
                int row = wm * 32 + mt * 16 + (mi & 1) * 8 + lr;
                int ch = ks * 2 + (mi >> 1);
                uint32_t off = (uint32_t)(row * 128 + ((ch ^ (row & 7)) * 16));
                LDSM4(afh[mt], sAh + off);
                LDSM4(afl[mt], sAl + off);
            }
            uint32_t bfh[4][4], bfl[4][4];
            #pragma unroll
            for (int pt = 0; pt < 4; pt++) {
                int row = wn * 64 + pt * 16 + (mi >> 1) * 8 + lr;
                int ch = ks * 2 + (mi & 1);
                uint32_t off = (uint32_t)(row * 128 + ((ch ^ (row & 7)) * 16));
                LDSM4(bfh[pt], sBh + off);
                LDSM4(bfl[pt], sBl + off);
            }
            #pragma unroll
            for (int mt = 0; mt < 2; mt++)
                #pragma unroll
                for (int nt = 0; nt < 8; nt++) {
                    uint32_t bh0 = bfh[nt >> 1][(nt & 1) * 2];
                    uint32_t bh1 = bfh[nt >> 1][(nt & 1) * 2 + 1];
                    uint32_t bl0 = bfl[nt >> 1][(nt & 1) * 2];
                    uint32_t bl1 = bfl[nt >> 1][(nt & 1) * 2 + 1];
                    MMA_BF16(acc[mt][nt], afh[mt], bh0, bh1);
                    MMA_BF16(acc[mt][nt], afh[mt], bl0, bl1);
                    MMA_BF16(acc[mt][nt], afl[mt], bh0, bh1);
                }
        }
        __syncthreads();
    }

    // Epilogue: acc + bias -> C
    int cr = lane >> 2;           // 0..7
    int cc = (lane & 3) * 2;
    #pragma unroll
    for (int mt = 0; mt < 2; mt++) {
        #pragma unroll
        for (int nt = 0; nt < 8; nt++) {
            int row = m0 + wm * 32 + mt * 16 + cr;
            int col = n0 + wn * 64 + nt * 8 + cc;
            float2 b01 = *reinterpret_cast<const float2*>(bias + col);
            float2 o0 = { acc[mt][nt][0] + b01.x, acc[mt][nt][1] + b01.y };
            float2 o1 = { acc[mt][nt][2] + b01.x, acc[mt][nt][3] + b01.y };
            *reinterpret_cast<float2*>(C + (size_t)row * N + col) = o0;
            *reinterpret_cast<float2*>(C + (size_t)(row + 8) * N + col) = o1;
        }
    }
}

// ---------------------------------------------------------------------------
// RMSNorm + RoPE
// ---------------------------------------------------------------------------
__global__ __launch_bounds__(256) void rmsnorm_rope_kernel(
    float* __restrict__ t, const float* __restrict__ g,
    const float* __restrict__ cs, const float* __restrict__ sn)
{
    int row = blockIdx.x;
    float* p = t + (size_t)row * DIM;

    __shared__ float sh[DIM];
    __shared__ float red[8];

    int tid = threadIdx.x;
    float4 v = *reinterpret_cast<const float4*>(&p[tid * 4]);
    float ss = v.x * v.x + v.y * v.y + v.z * v.z + v.w * v.w;
    #pragma unroll
    for (int o = 16; o; o >>= 1) ss += __shfl_xor_sync(0xFFFFFFFFu, ss, o);
    if ((tid & 31) == 0) red[tid >> 5] = ss;
    __syncthreads();
    if (tid == 0) {
        float tot = 0.f;
        #pragma unroll
        for (int i = 0; i < 8; i++) tot += red[i];
        red[0] = tot;
    }
    __syncthreads();
    float rms = rsqrtf(red[0] * (1.0f / DIM) + 1e-6f);

    float4 gv = *reinterpret_cast<const float4*>(&g[tid * 4]);
    sh[tid * 4 + 0] = v.x * rms * gv.x;
    sh[tid * 4 + 1] = v.y * rms * gv.y;
    sh[tid * 4 + 2] = v.z * rms * gv.z;
    sh[tid * 4 + 3] = v.w * rms * gv.w;
    __syncthreads();

    const float* crow = cs + (size_t)row * HEAD_DIM;
    const float* srow = sn + (size_t)row * HEAD_DIM;
    #pragma unroll
    for (int e = 0; e < 4; e++) {
        int i = tid * 4 + e;
        int d = i & (HEAD_DIM - 1);
        float n = sh[i];
        float other = (d < HEAD_DIM / 2) ? -sh[i + HEAD_DIM / 2]
                                         :  sh[i - HEAD_DIM / 2];
        p[i] = n * crow[d] + other * srow[d];
    }
}

// ---------------------------------------------------------------------------
// Flash attention (scalar fp32, unchanged)
// ---------------------------------------------------------------------------
__global__ __launch_bounds__(128) void attention_kernel(
    const float* __restrict__ q, const float* __restrict__ k,
    const float* __restrict__ v, float* __restrict__ o)
{
    int b = blockIdx.z;
    int h = blockIdx.y;
    int l = blockIdx.x * 128 + threadIdx.x;
    int tid = threadIdx.x;

    __shared__ float Ks[64][HEAD_DIM];
    __shared__ float Vs[64][HEAD_DIM];

    float qr[HEAD_DIM];
    float ov[HEAD_DIM];

    const float* qp = q + (((size_t)(b * LQ + l)) * NUM_HEADS + h) * HEAD_DIM;
    const float scale = 0.125f;
    #pragma unroll
    for (int d4 = 0; d4 < HEAD_DIM / 4; d4++) {
        float4 t = *reinterpret_cast<const float4*>(qp + d4 * 4);
        qr[d4 * 4 + 0] = t.x * scale;
        qr[d4 * 4 + 1] = t.y * scale;
        qr[d4 * 4 + 2] = t.z * scale;
        qr[d4 * 4 + 3] = t.w * scale;
    }
    #pragma unroll
    for (int d = 0; d < HEAD_DIM; d++) ov[d] = 0.f;
    float mi = -1e30f, li = 0.f;

    for (int m0 = 0; m0 < LKV; m0 += 64) {
        __syncthreads();
        #pragma unroll
        for (int i = 0; i < 8; i++) {
            int idx = tid * 8 + i;
            int m  = idx >> 4;
            int c4 = (idx & 15) * 4;
            size_t goff = (((size_t)(b * LKV + m0 + m)) * NUM_HEADS + h) * HEAD_DIM + c4;
            *reinterpret_cast<float4*>(&Ks[m][c4]) =
                *reinterpret_cast<const float4*>(&k[goff]);
            *reinterpret_cast<float4*>(&Vs[m][c4]) =
                *reinterpret_cast<const float4*>(&v[goff]);
        }
        __syncthreads();

        for (int m = 0; m < 64; m++) {
            const float4* K4 = reinterpret_cast<const float4*>(Ks[m]);
            float s = 0.f;
            #pragma unroll
            for (int d4 = 0; d4 < HEAD_DIM / 4; d4++) {
                float4 kv = K4[d4];
                s += qr[d4 * 4 + 0] * kv.x + qr[d4 * 4 + 1] * kv.y
                   + qr[d4 * 4 + 2] * kv.z + qr[d4 * 4 + 3] * kv.w;
            }
            if (s > mi) {
                float sc = __expf(mi - s);
                li *= sc;
                #pragma unroll
                for (int d = 0; d < HEAD_DIM; d++) ov[d] *= sc;
                mi = s;
            }
            float pexp = __expf(s - mi);
            li += pexp;
            const float4* V4 = reinterpret_cast<const float4*>(Vs[m]);
            #pragma unroll
            for (int d4 = 0; d4 < HEAD_DIM / 4; d4++) {
                float4 vv = V4[d4];
                ov[d4 * 4 + 0] += pexp * vv.x;
                ov[d4 * 4 + 1] += pexp * vv.y;
                ov[d4 * 4 + 2] += pexp * vv.z;
                ov[d4 * 4 + 3] += pexp * vv.w;
            }
        }
    }

    float inv = 1.0f / li;
    float* op = o + (((size_t)(b * LQ + l)) * NUM_HEADS + h) * HEAD_DIM;
    #pragma unroll
    for (int d4 = 0; d4 < HEAD_DIM / 4; d4++) {
        float4 t;
        t.x = ov[d4 * 4 + 0] * inv;
        t.y = ov[d4 * 4 + 1] * inv;
        t.z = ov[d4 * 4 + 2] * inv;
        t.w = ov[d4 * 4 + 3] * inv;
        *reinterpret_cast<float4*>(op + d4 * 4) = t;
    }
}

// ---------------------------------------------------------------------------
extern "C" void kernel_launch(void* const* d_in, const int* in_sizes, int n_in,
                              void* d_out, int out_size)
{
    const float* x     = (const float*)d_in[0];
    const float* y     = (const float*)d_in[1];
    const float* x_cos = (const float*)d_in[2];
    const float* x_sin = (const float*)d_in[3];
    const float* y_cos = (const float*)d_in[4];
    const float* y_sin = (const float*)d_in[5];
    const float* Wq    = (const float*)d_in[6];
    const float* bq    = (const float*)d_in[7];
    const float* Wk    = (const float*)d_in[8];
    const float* bk    = (const float*)d_in[9];
    const float* Wv    = (const float*)d_in[10];
    const float* bv    = (const float*)d_in[11];
    const float* Wo    = (const float*)d_in[12];
    const float* bo    = (const float*)d_in[13];
    const float* gq    = (const float*)d_in[14];
    const float* gk    = (const float*)d_in[15];
    float* out = (float*)d_out;

    float *q, *k, *v, *attn;
    cudaGetSymbolAddress((void**)&q,    g_q);
    cudaGetSymbolAddress((void**)&k,    g_k);
    cudaGetSymbolAddress((void**)&v,    g_v);
    cudaGetSymbolAddress((void**)&attn, g_attn);

    __nv_bfloat16 *xh, *xl, *yh, *yl, *ah, *al;
    __nv_bfloat16 *WqTh, *WqTl, *WkTh, *WkTl, *WvTh, *WvTl, *WoTh, *WoTl;
    cudaGetSymbolAddress((void**)&xh, g_xh);
    cudaGetSymbolAddress((void**)&xl, g_xl);
    cudaGetSymbolAddress((void**)&yh, g_yh);
    cudaGetSymbolAddress((void**)&yl, g_yl);
    cudaGetSymbolAddress((void**)&ah, g_ah);
    cudaGetSymbolAddress((void**)&al, g_al);
    cudaGetSymbolAddress((void**)&WqTh, g_WqTh);
    cudaGetSymbolAddress((void**)&WqTl, g_WqTl);
    cudaGetSymbolAddress((void**)&WkTh, g_WkTh);
    cudaGetSymbolAddress((void**)&WkTl, g_WkTl);
    cudaGetSymbolAddress((void**)&WvTh, g_WvTh);
    cudaGetSymbolAddress((void**)&WvTl, g_WvTl);
    cudaGetSymbolAddress((void**)&WoTh, g_WoTh);
    cudaGetSymbolAddress((void**)&WoTl, g_WoTl);

    cudaFuncSetAttribute(gemm_tc_kernel,
                         cudaFuncAttributeMaxDynamicSharedMemorySize, GEMM_SMEM);

    const int Mq = BATCH * LQ;    // 8192
    const int Mk = BATCH * LKV;   // 2048

    // Split activations to bf16 hi/lo
    split_kernel<<<(Mq * DIM) / 1024, 256>>>(x, xh, xl);
    split_kernel<<<(Mk * KV_DIM) / 1024, 256>>>(y, yh, yl);

    // Transpose + split weights: W[K,N] -> WT[N,K]
    transpose_split_kernel<<<dim3(DIM / 32, DIM / 32),    dim3(32, 8)>>>(Wq, WqTh, WqTl, DIM, DIM);
    transpose_split_kernel<<<dim3(DIM / 32, KV_DIM / 32), dim3(32, 8)>>>(Wk, WkTh, WkTl, KV_DIM, DIM);
    transpose_split_kernel<<<dim3(DIM / 32, KV_DIM / 32), dim3(32, 8)>>>(Wv, WvTh, WvTl, KV_DIM, DIM);
    transpose_split_kernel<<<dim3(DIM / 32, DIM / 32),    dim3(32, 8)>>>(Wo, WoTh, WoTl, DIM, DIM);

    // Projections on tensor cores (3xBF16 split)
    gemm_tc_kernel<<<dim3(8, Mq / 128), 256, GEMM_SMEM>>>(xh, xl, WqTh, WqTl, bq, q, Mq, DIM);
    gemm_tc_kernel<<<dim3(8, Mk / 128), 256, GEMM_SMEM>>>(yh, yl, WkTh, WkTl, bk, k, Mk, KV_DIM);
    gemm_tc_kernel<<<dim3(8, Mk / 128), 256, GEMM_SMEM>>>(yh, yl, WvTh, WvTl, bv, v, Mk, KV_DIM);

    // Norm + RoPE (in place, fp32)
    rmsnorm_rope_kernel<<<Mq, 256>>>(q, gq, x_cos, x_sin);
    rmsnorm_rope_kernel<<<Mk, 256>>>(k, gk, y_cos, y_sin);

    // Attention (scalar fp32)
    attention_kernel<<<dim3(LQ / 128, NUM_HEADS, BATCH), 128>>>(q, k, v, attn);

    // Output projection on tensor cores
    split_kernel<<<(Mq * DIM) / 1024, 256>>>(attn, ah, al);
    gemm_tc_kernel<<<dim3(8, Mq / 128), 256, GEMM_SMEM>>>(ah, al, WoTh, WoTl, bo, out, Mq, DIM);
}

// round 4
// speedup vs baseline: 1.6414x; 1.6414x over previous
#include <cuda_runtime.h>
#include <cuda_bf16.h>
#include <cstdint>

#define DIM 1024
#define KV_DIM 768
#define NUM_HEADS 16
#define HEAD_DIM 64
#define BATCH 2
#define LQ 4096
#define LKV 1024

// ---------------------------------------------------------------------------
// Scratch (no allocation allowed)
// ---------------------------------------------------------------------------
__device__ float g_q[BATCH * LQ * DIM];
__device__ float g_k[BATCH * LKV * DIM];
__device__ float g_v[BATCH * LKV * DIM];
__device__ float g_attn[BATCH * LQ * DIM];

__device__ __nv_bfloat16 g_xh[BATCH * LQ * DIM];
__device__ __nv_bfloat16 g_xl[BATCH * LQ * DIM];
__device__ __nv_bfloat16 g_yh[BATCH * LKV * KV_DIM];
__device__ __nv_bfloat16 g_yl[BATCH * LKV * KV_DIM];
__device__ __nv_bfloat16 g_ah[BATCH * LQ * DIM];
__device__ __nv_bfloat16 g_al[BATCH * LQ * DIM];
__device__ __nv_bfloat16 g_WqTh[DIM * DIM];
__device__ __nv_bfloat16 g_WqTl[DIM * DIM];
__device__ __nv_bfloat16 g_WkTh[DIM * KV_DIM];
__device__ __nv_bfloat16 g_WkTl[DIM * KV_DIM];
__device__ __nv_bfloat16 g_WvTh[DIM * KV_DIM];
__device__ __nv_bfloat16 g_WvTl[DIM * KV_DIM];
__device__ __nv_bfloat16 g_WoTh[DIM * DIM];
__device__ __nv_bfloat16 g_WoTl[DIM * DIM];

// ---------------------------------------------------------------------------
// mma.sync / ldmatrix / cp.async helpers (base-target sm_80+ features)
// ---------------------------------------------------------------------------
__device__ __forceinline__ uint32_t smem_u32(const void* p) {
    uint32_t a;
    asm("{ .reg .u64 t; cvta.to.shared.u64 t, %1; cvt.u32.u64 %0, t; }"
        : "=r"(a) : "l"(p));
    return a;
}

#define LDSM4(r, addr) \
    asm volatile("ldmatrix.sync.aligned.m8n8.x4.shared.b16 {%0,%1,%2,%3}, [%4];" \
        : "=r"((r)[0]), "=r"((r)[1]), "=r"((r)[2]), "=r"((r)[3]) : "r"(addr))

#define MMA_BF16(d, a, b0, b1) \
    asm volatile("mma.sync.aligned.m16n8k16.row.col.f32.bf16.bf16.f32 " \
        "{%0,%1,%2,%3}, {%4,%5,%6,%7}, {%8,%9}, {%0,%1,%2,%3};" \
        : "+f"((d)[0]), "+f"((d)[1]), "+f"((d)[2]), "+f"((d)[3]) \
        : "r"((a)[0]), "r"((a)[1]), "r"((a)[2]), "r"((a)[3]), "r"(b0), "r"(b1))

__device__ __forceinline__ void cp16(uint32_t dst, const void* src) {
    asm volatile("cp.async.cg.shared.global [%0], [%1], 16;"
                 :: "r"(dst), "l"(src) : "memory");
}

// ---------------------------------------------------------------------------
// Split fp32 -> bf16 hi + bf16 lo residual. n multiple of 1024.
// ---------------------------------------------------------------------------
__global__ __launch_bounds__(256) void split_kernel(
    const float* __restrict__ x, __nv_bfloat16* __restrict__ h,
    __nv_bfloat16* __restrict__ l)
{
    size_t i = ((size_t)blockIdx.x * 256 + threadIdx.x) * 4;
    float4 v = *reinterpret_cast<const float4*>(x + i);
    __nv_bfloat16 h0 = __float2bfloat16(v.x);
    __nv_bfloat16 h1 = __float2bfloat16(v.y);
    __nv_bfloat16 h2 = __float2bfloat16(v.z);
    __nv_bfloat16 h3 = __float2bfloat16(v.w);
    __nv_bfloat16 l0 = __float2bfloat16(v.x - __bfloat162float(h0));
    __nv_bfloat16 l1 = __float2bfloat16(v.y - __bfloat162float(h1));
    __nv_bfloat16 l2 = __float2bfloat16(v.z - __bfloat162float(h2));
    __nv_bfloat16 l3 = __float2bfloat16(v.w - __bfloat162float(h3));
    reinterpret_cast<__nv_bfloat162*>(h + i)[0] = __nv_bfloat162(h0, h1);
    reinterpret_cast<__nv_bfloat162*>(h + i)[1] = __nv_bfloat162(h2, h3);
    reinterpret_cast<__nv_bfloat162*>(l + i)[0] = __nv_bfloat162(l0, l1);
    reinterpret_cast<__nv_bfloat162*>(l + i)[1] = __nv_bfloat162(l2, l3);
}

// ---------------------------------------------------------------------------
// W [K,N] fp32 -> WT [N,K] bf16 hi/lo (transpose + split)
// ---------------------------------------------------------------------------
__global__ __launch_bounds__(256) void transpose_split_kernel(
    const float* __restrict__ W, __nv_bfloat16* __restrict__ Th,
    __nv_bfloat16* __restrict__ Tl, int K, int N)
{
    __shared__ float t[32][33];
    int n0 = blockIdx.x * 32, k0 = blockIdx.y * 32;
    int tx = threadIdx.x, ty = threadIdx.y;
    #pragma unroll
    for (int r = 0; r < 32; r += 8)
        t[ty + r][tx] = W[(size_t)(k0 + ty + r) * N + n0 + tx];
    __syncthreads();
    #pragma unroll
    for (int r = 0; r < 32; r += 8) {
        float v = t[tx][ty + r];
        __nv_bfloat16 hh = __float2bfloat16(v);
        __nv_bfloat16 ll = __float2bfloat16(v - __bfloat162float(hh));
        size_t o = (size_t)(n0 + ty + r) * K + k0 + tx;
        Th[o] = hh;
        Tl[o] = ll;
    }
}

// ---------------------------------------------------------------------------
// bf16 mma.sync GEMM, 3-term split: C = Ah@Bh^T + Ah@Bl^T + Al@Bh^T + bias
// CTA tile 128x128, K-chunk 32, 3-stage cp.async pipeline (32KB/stage, 96KB),
// 8 warps (4m x 2n), warp tile 32x64, __launch_bounds__(256,2) -> 2 CTA/SM.
// Smem tile: 128 rows x 64B, xor-swizzle (c ^ (r&3)) for ldmatrix.
// ---------------------------------------------------------------------------
#define TILE32_B  8192            // 128 x 32 bf16
#define STAGE_B   (4 * TILE32_B)  // Ah, Al, Bh, Bl = 32KB
#define GEMM_SMEM (3 * STAGE_B)   // 96KB

__device__ __forceinline__ void load_chunk32(
    uint32_t sbase,
    const __nv_bfloat16* __restrict__ Ah, const __nv_bfloat16* __restrict__ Al,
    const __nv_bfloat16* __restrict__ Bh, const __nv_bfloat16* __restrict__ Bl,
    int m0, int n0, int k0, int K, int tid)
{
    int rlo = tid >> 2;           // 0..63
    int c   = tid & 3;            // 16B chunk within 64B row
    #pragma unroll
    for (int t = 0; t < 8; t++) {
        int tile = t >> 1;                    // 0=Ah 1=Al 2=Bh 3=Bl
        int r = (t & 1) * 64 + rlo;           // row 0..127
        uint32_t off = (uint32_t)(tile * TILE32_B + r * 64 + ((c ^ (r & 3)) * 16));
        const __nv_bfloat16* src;
        size_t go;
        if (tile < 2) {
            src = (tile == 0) ? Ah : Al;
            go = (size_t)(m0 + r) * K + k0 + c * 8;
        } else {
            src = (tile == 2) ? Bh : Bl;
            go = (size_t)(n0 + r) * K + k0 + c * 8;
        }
        cp16(sbase + off, src + go);
    }
}

__global__ __launch_bounds__(256, 2) void gemm_tc_kernel(
    const __nv_bfloat16* __restrict__ Ah, const __nv_bfloat16* __restrict__ Al,
    const __nv_bfloat16* __restrict__ Bh, const __nv_bfloat16* __restrict__ Bl,
    const float* __restrict__ bias, float* __restrict__ C,
    int M, int K)
{
    extern __shared__ __align__(1024) char dsm[];
    const int N = 1024;
    int tid = threadIdx.x;
    int lane = tid & 31;
    int wid = tid >> 5;
    int wm = wid & 3;       // m-warp: 32 rows
    int wn = wid >> 2;      // n-warp: 64 cols
    int n0 = blockIdx.x * 128, m0 = blockIdx.y * 128;

    uint32_t sb = smem_u32(dsm);
    int nk = K >> 5;

    float acc[2][8][4];
    #pragma unroll
    for (int mt = 0; mt < 2; mt++)
        #pragma unroll
        for (int nt = 0; nt < 8; nt++)
            #pragma unroll
            for (int e = 0; e < 4; e++) acc[mt][nt][e] = 0.f;

    int mi = lane >> 3;     // ldmatrix sub-matrix index 0..3
    int lr = lane & 7;

    // Prologue: stages 0,1
    load_chunk32(sb, Ah, Al, Bh, Bl, m0, n0, 0, K, tid);
    asm volatile("cp.async.commit_group;" ::: "memory");
    load_chunk32(sb + STAGE_B, Ah, Al, Bh, Bl, m0, n0, 32, K, tid);
    asm volatile("cp.async.commit_group;" ::: "memory");

    int st = 0;            // stage of chunk i
    for (int i = 0; i < nk; i++) {
        asm volatile("cp.async.wait_group 1;" ::: "memory");
        __syncthreads();

        // Prefetch chunk i+2 into the stage freed at iter i-1
        int pst = st + 2; if (pst >= 3) pst -= 3;
        if (i + 2 < nk)
            load_chunk32(sb + pst * STAGE_B, Ah, Al, Bh, Bl, m0, n0,
                         (i + 2) << 5, K, tid);
        asm volatile("cp.async.commit_group;" ::: "memory");

        uint32_t base = sb + st * STAGE_B;
        uint32_t sAh = base, sAl = base + TILE32_B;
        uint32_t sBh = base + 2 * TILE32_B, sBl = base + 3 * TILE32_B;

        #pragma unroll
        for (int s = 0; s < 2; s++) {
            uint32_t afh[2][4], afl[2][4];
            #pragma unroll
            for (int mt = 0; mt < 2; mt++) {
                int row = wm * 32 + mt * 16 + (mi & 1) * 8 + lr;
                int ch = s * 2 + (mi >> 1);
                uint32_t off = (uint32_t)(row * 64 + ((ch ^ (row & 3)) * 16));
                LDSM4(afh[mt], sAh + off);
                LDSM4(afl[mt], sAl + off);
            }
            uint32_t bfh[4][4];
            #pragma unroll
            for (int pt = 0; pt < 4; pt++) {
                int row = wn * 64 + pt * 16 + (mi >> 1) * 8 + lr;
                int ch = s * 2 + (mi & 1);
                uint32_t off = (uint32_t)(row * 64 + ((ch ^ (row & 3)) * 16));
                LDSM4(bfh[pt], sBh + off);
            }
            // HH and LH terms (both use bfh)
            #pragma unroll
            for (int mt = 0; mt < 2; mt++)
                #pragma unroll
                for (int nt = 0; nt < 8; nt++) {
                    uint32_t b0 = bfh[nt >> 1][(nt & 1) * 2];
                    uint32_t b1 = bfh[nt >> 1][(nt & 1) * 2 + 1];
                    MMA_BF16(acc[mt][nt], afh[mt], b0, b1);
                    MMA_BF16(acc[mt][nt], afl[mt], b0, b1);
                }
            // HL term (loads bfl after bfh is dead -> lower reg pressure)
            uint32_t bfl[4][4];
            #pragma unroll
            for (int pt = 0; pt < 4; pt++) {
                int row = wn * 64 + pt * 16 + (mi >> 1) * 8 + lr;
                int ch = s * 2 + (mi & 1);
                uint32_t off = (uint32_t)(row * 64 + ((ch ^ (row & 3)) * 16));
                LDSM4(bfl[pt], sBl + off);
            }
            #pragma unroll
            for (int mt = 0; mt < 2; mt++)
                #pragma unroll
                for (int nt = 0; nt < 8; nt++) {
                    uint32_t b0 = bfl[nt >> 1][(nt & 1) * 2];
                    uint32_t b1 = bfl[nt >> 1][(nt & 1) * 2 + 1];
                    MMA_BF16(acc[mt][nt], afh[mt], b0, b1);
                }
        }
        __syncthreads();
        st = st + 1; if (st >= 3) st = 0;
    }

    // Epilogue: acc + bias -> C
    int cr = lane >> 2;
    int cc = (lane & 3) * 2;
    #pragma unroll
    for (int mt = 0; mt < 2; mt++) {
        #pragma unroll
        for (int nt = 0; nt < 8; nt++) {
            int row = m0 + wm * 32 + mt * 16 + cr;
            int col = n0 + wn * 64 + nt * 8 + cc;
            float2 b01 = *reinterpret_cast<const float2*>(bias + col);
            float2 o0 = { acc[mt][nt][0] + b01.x, acc[mt][nt][1] + b01.y };
            float2 o1 = { acc[mt][nt][2] + b01.x, acc[mt][nt][3] + b01.y };
            *reinterpret_cast<float2*>(C + (size_t)row * N + col) = o0;
            *reinterpret_cast<float2*>(C + (size_t)(row + 8) * N + col) = o1;
        }
    }
}

// ---------------------------------------------------------------------------
// RMSNorm + RoPE
// ---------------------------------------------------------------------------
__global__ __launch_bounds__(256) void rmsnorm_rope_kernel(
    float* __restrict__ t, const float* __restrict__ g,
    const float* __restrict__ cs, const float* __restrict__ sn)
{
    int row = blockIdx.x;
    float* p = t + (size_t)row * DIM;

    __shared__ float sh[DIM];
    __shared__ float red[8];

    int tid = threadIdx.x;
    float4 v = *reinterpret_cast<const float4*>(&p[tid * 4]);
    float ss = v.x * v.x + v.y * v.y + v.z * v.z + v.w * v.w;
    #pragma unroll
    for (int o = 16; o; o >>= 1) ss += __shfl_xor_sync(0xFFFFFFFFu, ss, o);
    if ((tid & 31) == 0) red[tid >> 5] = ss;
    __syncthreads();
    if (tid == 0) {
        float tot = 0.f;
        #pragma unroll
        for (int i = 0; i < 8; i++) tot += red[i];
        red[0] = tot;
    }
    __syncthreads();
    float rms = rsqrtf(red[0] * (1.0f / DIM) + 1e-6f);

    float4 gv = *reinterpret_cast<const float4*>(&g[tid * 4]);
    sh[tid * 4 + 0] = v.x * rms * gv.x;
    sh[tid * 4 + 1] = v.y * rms * gv.y;
    sh[tid * 4 + 2] = v.z * rms * gv.z;
    sh[tid * 4 + 3] = v.w * rms * gv.w;
    __syncthreads();

    const float* crow = cs + (size_t)row * HEAD_DIM;
    const float* srow = sn + (size_t)row * HEAD_DIM;
    #pragma unroll
    for (int e = 0; e < 4; e++) {
        int i = tid * 4 + e;
        int d = i & (HEAD_DIM - 1);
        float n = sh[i];
        float other = (d < HEAD_DIM / 2) ? -sh[i + HEAD_DIM / 2]
                                         :  sh[i - HEAD_DIM / 2];
        p[i] = n * crow[d] + other * srow[d];
    }
}

// ---------------------------------------------------------------------------
// Flash attention (scalar fp32)
// ---------------------------------------------------------------------------
__global__ __launch_bounds__(128) void attention_kernel(
    const float* __restrict__ q, const float* __restrict__ k,
    const float* __restrict__ v, float* __restrict__ o)
{
    int b = blockIdx.z;
    int h = blockIdx.y;
    int l = blockIdx.x * 128 + threadIdx.x;
    int tid = threadIdx.x;

    __shared__ float Ks[64][HEAD_DIM];
    __shared__ float Vs[64][HEAD_DIM];

    float qr[HEAD_DIM];
    float ov[HEAD_DIM];

    const float* qp = q + (((size_t)(b * LQ + l)) * NUM_HEADS + h) * HEAD_DIM;
    const float scale = 0.125f;
    #pragma unroll
    for (int d4 = 0; d4 < HEAD_DIM / 4; d4++) {
        float4 t = *reinterpret_cast<const float4*>(qp + d4 * 4);
        qr[d4 * 4 + 0] = t.x * scale;
        qr[d4 * 4 + 1] = t.y * scale;
        qr[d4 * 4 + 2] = t.z * scale;
        qr[d4 * 4 + 3] = t.w * scale;
    }
    #pragma unroll
    for (int d = 0; d < HEAD_DIM; d++) ov[d] = 0.f;
    float mi = -1e30f, li = 0.f;

    for (int m0 = 0; m0 < LKV; m0 += 64) {
        __syncthreads();
        #pragma unroll
        for (int i = 0; i < 8; i++) {
            int idx = tid * 8 + i;
            int m  = idx >> 4;
            int c4 = (idx & 15) * 4;
            size_t goff = (((size_t)(b * LKV + m0 + m)) * NUM_HEADS + h) * HEAD_DIM + c4;
            *reinterpret_cast<float4*>(&Ks[m][c4]) =
                *reinterpret_cast<const float4*>(&k[goff]);
            *reinterpret_cast<float4*>(&Vs[m][c4]) =
                *reinterpret_cast<const float4*>(&v[goff]);
        }
        __syncthreads();

        for (int m = 0; m < 64; m++) {
            const float4* K4 = reinterpret_cast<const float4*>(Ks[m]);
            float s = 0.f;
            #pragma unroll
            for (int d4 = 0; d4 < HEAD_DIM / 4; d4++) {
                float4 kv = K4[d4];
                s += qr[d4 * 4 + 0] * kv.x + qr[d4 * 4 + 1] * kv.y
                   + qr[d4 * 4 + 2] * kv.z + qr[d4 * 4 + 3] * kv.w;
            }
            if (s > mi) {
                float sc = __expf(mi - s);
                li *= sc;
                #pragma unroll
                for (int d = 0; d < HEAD_DIM; d++) ov[d] *= sc;
                mi = s;
            }
            float pexp = __expf(s - mi);
            li += pexp;
            const float4* V4 = reinterpret_cast<const float4*>(Vs[m]);
            #pragma unroll
            for (int d4 = 0; d4 < HEAD_DIM / 4; d4++) {
                float4 vv = V4[d4];
                ov[d4 * 4 + 0] += pexp * vv.x;
                ov[d4 * 4 + 1] += pexp * vv.y;
                ov[d4 * 4 + 2] += pexp * vv.z;
                ov[d4 * 4 + 3] += pexp * vv.w;
            }
        }
    }

    float inv = 1.0f / li;
    float* op = o + (((size_t)(b * LQ + l)) * NUM_HEADS + h) * HEAD_DIM;
    #pragma unroll
    for (int d4 = 0; d4 < HEAD_DIM / 4; d4++) {
        float4 t;
        t.x = ov[d4 * 4 + 0] * inv;
        t.y = ov[d4 * 4 + 1] * inv;
        t.z = ov[d4 * 4 + 2] * inv;
        t.w = ov[d4 * 4 + 3] * inv;
        *reinterpret_cast<float4*>(op + d4 * 4) = t;
    }
}

// ---------------------------------------------------------------------------
extern "C" void kernel_launch(void* const* d_in, const int* in_sizes, int n_in,
                              void* d_out, int out_size)
{
    const float* x     = (const float*)d_in[0];
    const float* y     = (const float*)d_in[1];
    const float* x_cos = (const float*)d_in[2];
    const float* x_sin = (const float*)d_in[3];
    const float* y_cos = (const float*)d_in[4];
    const float* y_sin = (const float*)d_in[5];
    const float* Wq    = (const float*)d_in[6];
    const float* bq    = (const float*)d_in[7];
    const float* Wk    = (const float*)d_in[8];
    const float* bk    = (const float*)d_in[9];
    const float* Wv    = (const float*)d_in[10];
    const float* bv    = (const float*)d_in[11];
    const float* Wo    = (const float*)d_in[12];
    const float* bo    = (const float*)d_in[13];
    const float* gq    = (const float*)d_in[14];
    const float* gk    = (const float*)d_in[15];
    float* out = (float*)d_out;

    float *q, *k, *v, *attn;
    cudaGetSymbolAddress((void**)&q,    g_q);
    cudaGetSymbolAddress((void**)&k,    g_k);
    cudaGetSymbolAddress((void**)&v,    g_v);
    cudaGetSymbolAddress((void**)&attn, g_attn);

    __nv_bfloat16 *xh, *xl, *yh, *yl, *ah, *al;
    __nv_bfloat16 *WqTh, *WqTl, *WkTh, *WkTl, *WvTh, *WvTl, *WoTh, *WoTl;
    cudaGetSymbolAddress((void**)&xh, g_xh);
    cudaGetSymbolAddress((void**)&xl, g_xl);
    cudaGetSymbolAddress((void**)&yh, g_yh);
    cudaGetSymbolAddress((void**)&yl, g_yl);
    cudaGetSymbolAddress((void**)&ah, g_ah);
    cudaGetSymbolAddress((void**)&al, g_al);
    cudaGetSymbolAddress((void**)&WqTh, g_WqTh);
    cudaGetSymbolAddress((void**)&WqTl, g_WqTl);
    cudaGetSymbolAddress((void**)&WkTh, g_WkTh);
    cudaGetSymbolAddress((void**)&WkTl, g_WkTl);
    cudaGetSymbolAddress((void**)&WvTh, g_WvTh);
    cudaGetSymbolAddress((void**)&WvTl, g_WvTl);
    cudaGetSymbolAddress((void**)&WoTh, g_WoTh);
    cudaGetSymbolAddress((void**)&WoTl, g_WoTl);

    cudaFuncSetAttribute(gemm_tc_kernel,
                         cudaFuncAttributeMaxDynamicSharedMemorySize, GEMM_SMEM);

    const int Mq = BATCH * LQ;    // 8192
    const int Mk = BATCH * LKV;   // 2048

    // Launch order matters for ncu (-s 5 -c 1): 6th launch = Q GEMM.
    split_kernel<<<(Mq * DIM) / 1024, 256>>>(x, xh, xl);                                    // 0
    split_kernel<<<(Mk * KV_DIM) / 1024, 256>>>(y, yh, yl);                                 // 1
    transpose_split_kernel<<<dim3(DIM / 32, DIM / 32),    dim3(32, 8)>>>(Wq, WqTh, WqTl, DIM, DIM);     // 2
    transpose_split_kernel<<<dim3(DIM / 32, KV_DIM / 32), dim3(32, 8)>>>(Wk, WkTh, WkTl, KV_DIM, DIM);  // 3
    transpose_split_kernel<<<dim3(DIM / 32, KV_DIM / 32), dim3(32, 8)>>>(Wv, WvTh, WvTl, KV_DIM, DIM);  // 4

    gemm_tc_kernel<<<dim3(8, Mq / 128), 256, GEMM_SMEM>>>(xh, xl, WqTh, WqTl, bq, q, Mq, DIM);          // 5 <- ncu
    gemm_tc_kernel<<<dim3(8, Mk / 128), 256, GEMM_SMEM>>>(yh, yl, WkTh, WkTl, bk, k, Mk, KV_DIM);
    gemm_tc_kernel<<<dim3(8, Mk / 128), 256, GEMM_SMEM>>>(yh, yl, WvTh, WvTl, bv, v, Mk, KV_DIM);

    rmsnorm_rope_kernel<<<Mq, 256>>>(q, gq, x_cos, x_sin);
    rmsnorm_rope_kernel<<<Mk, 256>>>(k, gk, y_cos, y_sin);

    attention_kernel<<<dim3(LQ / 128, NUM_HEADS, BATCH), 128>>>(q, k, v, attn);

    transpose_split_kernel<<<dim3(DIM / 32, DIM / 32), dim3(32, 8)>>>(Wo, WoTh, WoTl, DIM, DIM);
    split_kernel<<<(Mq * DIM) / 1024, 256>>>(attn, ah, al);
    gemm_tc_kernel<<<dim3(8, Mq / 128), 256, GEMM_SMEM>>>(ah, al, WoTh, WoTl, bo, out, Mq, DIM);
}